// round 4
// baseline (speedup 1.0000x reference)
#include <cuda_runtime.h>
#include <cuda_bf16.h>

namespace {

constexpr int IMW = 1024;
constexpr int IMH = 1024;
constexpr int PY  = 16;       // output rows per thread (processed in vertical pairs)
constexpr int YB  = 4;        // blockDim.y
constexpr int ROWS_PER_BLOCK = YB * PY;          // 64
constexpr int NYB = IMH / ROWS_PER_BLOCK;        // 16 y-blocks

__device__ __forceinline__ void s2(float &a, float &b) {
    float t = fminf(a, b);
    b = fmaxf(a, b);
    a = t;
}

// 9-comparator sort5 (Batcher sort4 + insertion chain).
__device__ __forceinline__ void sort5(float v[5]) {
    s2(v[0], v[1]); s2(v[2], v[3]); s2(v[0], v[2]); s2(v[1], v[3]); s2(v[1], v[2]);
    s2(v[3], v[4]); s2(v[2], v[3]); s2(v[1], v[2]); s2(v[0], v[1]);
}

// 5-comparator sort4.
__device__ __forceinline__ void sort4(float &a, float &b, float &c, float &d) {
    s2(a, b); s2(c, d); s2(a, c); s2(b, d); s2(b, c);
}

// Place min at m[0], max at m[K-1]; multiset preserved, middles intact.
template <int K>
__device__ __forceinline__ void minmaxK(float *m) {
    if constexpr ((K & 1) == 0) {
        #pragma unroll
        for (int i = 0; i < K; i += 2) s2(m[i], m[i + 1]);
        #pragma unroll
        for (int i = 2; i < K; i += 2) s2(m[0], m[i]);
        #pragma unroll
        for (int i = 1; i < K - 1; i += 2) s2(m[i], m[K - 1]);
    } else {
        #pragma unroll
        for (int i = 0; i + 1 < K; i += 2) s2(m[i], m[i + 1]);
        s2(m[K - 2], m[K - 1]);
        #pragma unroll
        for (int i = 2; i <= K - 3; i += 2) s2(m[0], m[i]);
        s2(m[0], m[K - 2]);
        #pragma unroll
        for (int i = 1; i <= K - 4; i += 2) s2(m[i], m[K - 1]);
    }
}

__device__ __forceinline__ float med3f(float a, float b, float c) {
    return fmaxf(fminf(a, b), fminf(fmaxf(a, b), c));
}

// Median of the 13 doubly-sorted candidates.
// Known preorders exploited in stage 1: t1a<=t1b (col1 q2<=q3), t2a<=t2b (col2 q1<=q2).
__device__ __forceinline__ float median13(
    float t0a, float t0b,                     // col0 top2 (unordered)
    float t1a, float t1b, float t1c,          // col1 top3, t1a<=t1b
    float t2a, float t2b, float t2c,          // col2 mid3, t2a<=t2b
    float t3a, float t3b, float t3c,          // col3 bot3
    float t4a, float t4b)                     // col4 bot2
{
    // minmax of 8 = {t0a,t0b,t1a,t1b,t1c,t2a,t2b,t2c} in 8 swaps.
    float l2 = t0a, h2 = t0b; s2(l2, h2);
    float l3 = t1c, h3 = t2c; s2(l3, h3);
    float l0 = t1a, l1 = t2a, h0 = t1b, h1 = t2b;
    s2(l0, l1); s2(l0, l2); s2(l0, l3);   // l0 = min of 8 (dropped)
    s2(h0, h1); s2(h1, h2); s2(h2, h3);   // h3 = max of 8 (dropped)

    float m[7];
    m[0] = l1; m[1] = l2; m[2] = l3; m[3] = h0; m[4] = h1; m[5] = h2;
    m[6] = t3a; minmaxK<7>(m);       // middle: m[1..5]
    m[6] = t3b; minmaxK<6>(m + 1);   // middle: m[2..5]
    m[6] = t3c; minmaxK<5>(m + 2);   // middle: m[3..5]
    m[6] = t4a; minmaxK<4>(m + 3);   // middle: m[4..5]
    m[6] = t4b;
    return med3f(m[4], m[5], m[6]);
}

template <bool Y_SAFE>
__global__ void __launch_bounds__(128)
median5x5_kernel(const float* __restrict__ in, float* __restrict__ out, int yblk0) {
    const int x  = blockIdx.x * 32 + threadIdx.x;
    int yb = blockIdx.y + yblk0;
    if (!Y_SAFE && yblk0 < 0) {
        // Edge launch: blockIdx.y {0,1} -> y-blocks {0, NYB-1}.
        yb = blockIdx.y * (NYB - 1);
    }
    const int y0 = yb * ROWS_PER_BLOCK + threadIdx.y * PY;
    const long imgoff = (long)blockIdx.z << 20;  // 1024*1024 per image
    const float* img = in + imgoff;
    float* outp = out + imgoff + x;

    const bool okm2 = (x >= 2);
    const bool okm1 = (x >= 1);
    const bool okp1 = (x <= IMW - 2);
    const bool okp2 = (x <= IMW - 3);

    auto load_row = [&](int yy, float v[5]) {
        if (Y_SAFE || (unsigned)yy < (unsigned)IMH) {
            const float* p = img + yy * IMW + x;
            v[0] = okm2 ? __ldg(p - 2) : 0.0f;
            v[1] = okm1 ? __ldg(p - 1) : 0.0f;
            v[2] = __ldg(p);
            v[3] = okp1 ? __ldg(p + 1) : 0.0f;
            v[4] = okp2 ? __ldg(p + 2) : 0.0f;
        } else {
            v[0] = v[1] = v[2] = v[3] = v[4] = 0.0f;
        }
    };

    // Sorted horizontal 5-windows. For the pair (y, y+1):
    // r0 = y-2 (private to pixel A), r1..r4 = y-1..y+2 (common), r5 = y+3 (private to B).
    float r0[5], r1[5], r2[5], r3[5], r4[5], r5[5];
    load_row(y0 - 2, r0); sort5(r0);
    load_row(y0 - 1, r1); sort5(r1);
    load_row(y0 + 0, r2); sort5(r2);
    load_row(y0 + 1, r3); sort5(r3);

    #pragma unroll
    for (int p = 0; p < PY; p += 2) {
        const int y = y0 + p;
        load_row(y + 2, r4); sort5(r4);
        load_row(y + 3, r5); sort5(r5);

        // Shared per-column sort4 of the 4 common rows.
        float q[5][4];
        #pragma unroll
        for (int j = 0; j < 5; ++j) {
            q[j][0] = r1[j]; q[j][1] = r2[j]; q[j][2] = r3[j]; q[j][3] = r4[j];
            sort4(q[j][0], q[j][1], q[j][2], q[j][3]);
        }

        // O(1) merge of each pixel's private element into the required rank sets.
        // col j keeps column-ranks: j=0:{3,4} j=1:{2,3,4} j=2:{1,2,3} j=3:{0,1,2} j=4:{0,1}.
        #pragma unroll
        for (int pix = 0; pix < 2; ++pix) {
            const float* rp = pix ? r5 : r0;
            float a0 = rp[0], a1 = rp[1], a2 = rp[2], a3 = rp[3], a4 = rp[4];

            float t0a = q[0][3];
            float t0b = fmaxf(q[0][2], a0);

            float t1a = q[1][2], t1b = q[1][3];
            float t1c = fmaxf(q[1][1], a1);

            float t2a = q[2][1], t2b = q[2][2];
            float t2c = fminf(fmaxf(a2, q[2][0]), q[2][3]);   // clamp

            float t3a = q[3][0], t3b = q[3][1];
            float t3c = fminf(q[3][2], a3);

            float t4a = q[4][0];
            float t4b = fminf(q[4][1], a4);

            float med = median13(t0a, t0b, t1a, t1b, t1c,
                                 t2a, t2b, t2c, t3a, t3b, t3c, t4a, t4b);
            outp[(y + pix) * IMW] = med;
        }

        // Slide window down two rows (renamed away under full unroll).
        #pragma unroll
        for (int j = 0; j < 5; ++j) {
            r0[j] = r2[j]; r1[j] = r3[j]; r2[j] = r4[j]; r3[j] = r5[j];
        }
    }
}

}  // namespace

extern "C" void kernel_launch(void* const* d_in, const int* in_sizes, int n_in,
                              void* d_out, int out_size) {
    const float* x = (const float*)d_in[0];
    float* out = (float*)d_out;
    const int nimg = out_size / (IMW * IMH);   // B*C = 8
    dim3 block(32, YB, 1);

    // Interior y-blocks 1..NYB-2: no y-bound checks needed
    // (rows 62..961 read rows 60..963, all in range).
    dim3 grid_int(IMW / 32, NYB - 2, nimg);
    median5x5_kernel<true><<<grid_int, block>>>(x, out, 1);

    // Edge y-blocks {0, NYB-1}: full y checks.
    dim3 grid_edge(IMW / 32, 2, nimg);
    median5x5_kernel<false><<<grid_edge, block>>>(x, out, -1);
}